// round 5
// baseline (speedup 1.0000x reference)
#include <cuda_runtime.h>
#include <cstdint>

#define N_TOK 8192
#define HID   8192
#define NG    16
#define NE    16

#define BM      64
#define BK      64
#define NSTAGE  (HID / BK)        // 128
#define NBUF    4

// stage: X 64 tok x 256B (swizzled) = 16384 ; W hi 4KB + lo 4KB = 8192
#define STAGE_B  24576
#define W_OFF    16384
#define RING_B   (NBUF * STAGE_B)   // 98304 dynamic smem

typedef unsigned long long ull;

// ---------------- device scratch ----------------
__device__ float d_w1hi[HID * NG];     // [k][g]
__device__ float d_w1lo[HID * NG];
__device__ float d_wmhi[NG * HID * NE];  // [g][k][e] (same layout as input)
__device__ float d_wmlo[NG * HID * NE];
__device__ float d_gsum[NG];
__device__ float d_msum[NE];
__device__ int   d_gsel[N_TOK];
__device__ int   d_gcount[NG];
__device__ int   d_goff[NG];
__device__ int   d_gcur[NG];
__device__ int   d_perm[N_TOK];

// ---------------- helpers ----------------
__device__ __forceinline__ uint32_t s2u(const void* p) {
    return (uint32_t)__cvta_generic_to_shared(p);
}
__device__ __forceinline__ void cp16(uint32_t dst, const void* src) {
    asm volatile("cp.async.cg.shared.global [%0], [%1], 16;" :: "r"(dst), "l"(src));
}
#define CP_COMMIT() asm volatile("cp.async.commit_group;" ::: "memory")
#define CP_WAIT2()  asm volatile("cp.async.wait_group 2;" ::: "memory")

__device__ __forceinline__ uint32_t tf32c(float x) {
    uint32_t u;
    asm("cvt.rna.tf32.f32 %0, %1;" : "=r"(u) : "f"(x));
    return u;
}
__device__ __forceinline__ void mma8(float* d, const uint32_t* a, const uint32_t* b) {
    asm volatile(
        "mma.sync.aligned.m16n8k8.row.col.f32.tf32.tf32.f32 "
        "{%0,%1,%2,%3}, {%4,%5,%6,%7}, {%8,%9}, {%0,%1,%2,%3};"
        : "+f"(d[0]), "+f"(d[1]), "+f"(d[2]), "+f"(d[3])
        : "r"(a[0]), "r"(a[1]), "r"(a[2]), "r"(a[3]), "r"(b[0]), "r"(b[1]));
}

// ============================================================
// Prep: split W1 (transposed) and WM into tf32 hi/lo
// ============================================================
__global__ void k_prep_w1(const float* __restrict__ W1)
{
    const int k = blockIdx.x * 256 + threadIdx.x;   // 32 blocks
#pragma unroll
    for (int g = 0; g < NG; g++) {
        float v = W1[(size_t)g * HID + k];
        uint32_t h = tf32c(v);
        float hf = __uint_as_float(h);
        d_w1hi[(size_t)k * NG + g] = hf;
        d_w1lo[(size_t)k * NG + g] = __uint_as_float(tf32c(v - hf));
    }
    if (blockIdx.x == 0 && threadIdx.x < NG) {
        d_gsum[threadIdx.x] = 0.f;
        d_msum[threadIdx.x] = 0.f;
        d_gcount[threadIdx.x] = 0;
    }
}

__global__ void k_prep_wm(const float* __restrict__ WM)
{
    const size_t i = ((size_t)blockIdx.x * 256 + threadIdx.x) * 4;   // 2048 blocks
    float4 v = *reinterpret_cast<const float4*>(WM + i);
    float4 h, l;
    h.x = __uint_as_float(tf32c(v.x)); l.x = __uint_as_float(tf32c(v.x - h.x));
    h.y = __uint_as_float(tf32c(v.y)); l.y = __uint_as_float(tf32c(v.y - h.y));
    h.z = __uint_as_float(tf32c(v.z)); l.z = __uint_as_float(tf32c(v.z - h.z));
    h.w = __uint_as_float(tf32c(v.w)); l.w = __uint_as_float(tf32c(v.w - h.w));
    *reinterpret_cast<float4*>(d_wmhi + i) = h;
    *reinterpret_cast<float4*>(d_wmlo + i) = l;
}

// ============================================================
// Core mainloop (shared by both GEMMs). Produces red[64][17] logits.
//   xs       : per-thread X gmem src (row base + chunk offset), +s*256/stage
//   whs, wls : per-thread W hi/lo gmem src, +s*4096/stage
// ============================================================
__device__ __forceinline__ void gemm_core(char* sm, const char* xs,
                                          const char* whs, const char* wls,
                                          int tid, float* red)
{
    const int l = tid & 31, wid = tid >> 5;
    const int mw = wid & 1, kg = wid >> 1;          // m32-half, k-split slice
    const int r = l >> 2, c = l & 3;
    const int kl = l & 3, m = l >> 2, nh = m >> 2, wl = m & 3;

    // loader dst offsets (within stage slot)
    const int ltok = tid >> 2, lch = tid & 3;
    const uint32_t smb = s2u(sm);
    uint32_t xd[4];
#pragma unroll
    for (int j = 0; j < 4; j++)
        xd[j] = ltok * 256 + (((lch + 4 * j) ^ (ltok & 7)) * 16);
    const int lk = tid >> 2, lc = tid & 3;
    const uint32_t wdh = W_OFF + lk * 64 + ((lc ^ (lk & 3)) * 16);
    const uint32_t wdl = wdh + 4096;

    // A fragment smem offsets: [mt][j][chunk-pair]
    uint32_t offA[2][2][2];
#pragma unroll
    for (int mt = 0; mt < 2; mt++)
#pragma unroll
        for (int j = 0; j < 2; j++)
#pragma unroll
            for (int p = 0; p < 2; p++)
                offA[mt][j][p] = (mw * 32 + mt * 16 + r) * 256 +
                                 (((kg * 4 + j * 2 + p) ^ r) * 16) + c * 4;
    // B fragment smem offsets: [j][split][ntile]
    uint32_t offB[2][2][2];
#pragma unroll
    for (int j = 0; j < 2; j++)
#pragma unroll
        for (int sp = 0; sp < 2; sp++)
#pragma unroll
            for (int nt = 0; nt < 2; nt++)
                offB[j][sp][nt] = W_OFF + sp * 4096 +
                                  ((kg * 2 + j) * 8 + kl) * 64 +
                                  (((nt * 2 + nh) ^ kl) * 16) + wl * 4;

    float acc[2][2][4];
#pragma unroll
    for (int a = 0; a < 2; a++)
#pragma unroll
        for (int b = 0; b < 2; b++)
#pragma unroll
            for (int q = 0; q < 4; q++) acc[a][b][q] = 0.f;

#define GISSUE(s_) do {                                                  \
        uint32_t b_ = ((s_) & 3) * STAGE_B;                              \
        const char* xp_ = xs + (size_t)(s_) * 256;                       \
        cp16(smb + b_ + xd[0], xp_);                                     \
        cp16(smb + b_ + xd[1], xp_ + 64);                                \
        cp16(smb + b_ + xd[2], xp_ + 128);                               \
        cp16(smb + b_ + xd[3], xp_ + 192);                               \
        cp16(smb + b_ + wdh, whs + (size_t)(s_) * 4096);                 \
        cp16(smb + b_ + wdl, wls + (size_t)(s_) * 4096);                 \
    } while (0)

    GISSUE(0); CP_COMMIT();
    GISSUE(1); CP_COMMIT();
    GISSUE(2); CP_COMMIT();

    for (int s = 0; s < NSTAGE; s++) {
        CP_WAIT2();
        __syncthreads();
        if (s + 3 < NSTAGE) GISSUE(s + 3);
        CP_COMMIT();

        const char* bb = sm + (s & 3) * STAGE_B;
#pragma unroll
        for (int j = 0; j < 2; j++) {
            uint32_t bh[2][2], bl[2][2];
#pragma unroll
            for (int nt = 0; nt < 2; nt++) {
                bh[nt][0] = *(const uint32_t*)(bb + offB[j][0][nt]);
                bh[nt][1] = *(const uint32_t*)(bb + offB[j][0][nt] + 256);
                bl[nt][0] = *(const uint32_t*)(bb + offB[j][1][nt]);
                bl[nt][1] = *(const uint32_t*)(bb + offB[j][1][nt] + 256);
            }
#pragma unroll
            for (int mt = 0; mt < 2; mt++) {
                float a0 = *(const float*)(bb + offA[mt][j][0]);
                float a1 = *(const float*)(bb + offA[mt][j][0] + 2048);
                float a2 = *(const float*)(bb + offA[mt][j][1]);
                float a3 = *(const float*)(bb + offA[mt][j][1] + 2048);
                uint32_t ah[4], al[4];
                ah[0] = tf32c(a0); al[0] = tf32c(a0 - __uint_as_float(ah[0]));
                ah[1] = tf32c(a1); al[1] = tf32c(a1 - __uint_as_float(ah[1]));
                ah[2] = tf32c(a2); al[2] = tf32c(a2 - __uint_as_float(ah[2]));
                ah[3] = tf32c(a3); al[3] = tf32c(a3 - __uint_as_float(ah[3]));
#pragma unroll
                for (int nt = 0; nt < 2; nt++) {
                    mma8(acc[mt][nt], ah, bh[nt]);
                    mma8(acc[mt][nt], ah, bl[nt]);
                    mma8(acc[mt][nt], al, bh[nt]);
                }
            }
        }
    }
#undef GISSUE

    // ---- reduce k-split-4 partials into red[64][17] ----
    for (int q = 0; q < 4; q++) {
        if (kg == q) {
#pragma unroll
            for (int mt = 0; mt < 2; mt++)
#pragma unroll
                for (int nt = 0; nt < 2; nt++) {
                    const int r0 = mw * 32 + mt * 16 + (l >> 2);
                    const int cc = nt * 8 + 2 * (l & 3);
                    float* dd = acc[mt][nt];
                    if (q == 0) {
                        red[r0 * 17 + cc] = dd[0];
                        red[r0 * 17 + cc + 1] = dd[1];
                        red[(r0 + 8) * 17 + cc] = dd[2];
                        red[(r0 + 8) * 17 + cc + 1] = dd[3];
                    } else {
                        red[r0 * 17 + cc] += dd[0];
                        red[r0 * 17 + cc + 1] += dd[1];
                        red[(r0 + 8) * 17 + cc] += dd[2];
                        red[(r0 + 8) * 17 + cc + 1] += dd[3];
                    }
                }
        }
        __syncthreads();
    }
}

// ============================================================
// Kernel 1: group-gate GEMM + softmax/argmax/sums/hist
// ============================================================
__global__ void __launch_bounds__(256, 2)
k_gemm1(const float* __restrict__ X)
{
    extern __shared__ __align__(16) char sm[];
    __shared__ int shist[NG];
    const int tid = threadIdx.x;
    if (tid < NG) shist[tid] = 0;

    const char* xs = (const char*)(X + (size_t)(blockIdx.x * BM + (tid >> 2)) * HID)
                     + (tid & 3) * 16;
    const char* whs = (const char*)d_w1hi + (tid >> 2) * 64 + (tid & 3) * 16;
    const char* wls = (const char*)d_w1lo + (tid >> 2) * 64 + (tid & 3) * 16;

    float* red = (float*)sm;
    gemm_core(sm, xs, whs, wls, tid, red);

    float* pb = (float*)(sm + 4608);   // [64][17]
    if (tid < BM) {
        float lg[NG];
#pragma unroll
        for (int g = 0; g < NG; g++) lg[g] = red[tid * 17 + g];
        float mx = lg[0];
        int gi = 0;
#pragma unroll
        for (int g = 1; g < NG; g++)
            if (lg[g] > mx) { mx = lg[g]; gi = g; }
        float p[NG], ss = 0.f;
#pragma unroll
        for (int g = 0; g < NG; g++) { p[g] = __expf(lg[g] - mx); ss += p[g]; }
        const float inv = 1.0f / ss;
#pragma unroll
        for (int g = 0; g < NG; g++) pb[tid * 17 + g] = p[g] * inv;
        d_gsel[blockIdx.x * BM + tid] = gi;
        atomicAdd(&shist[gi], 1);
    }
    __syncthreads();
    if (tid < NG) {
        float s = 0.f;
        for (int t = 0; t < BM; t++) s += pb[t * 17 + tid];
        atomicAdd(&d_gsum[tid], s);
        atomicAdd(&d_gcount[tid], shist[tid]);
    }
}

// ============================================================
// Sorting pipeline
// ============================================================
__global__ void k_prefix()
{
    if (threadIdx.x == 0) {
        int a = 0;
        for (int g = 0; g < NG; g++) { d_goff[g] = a; d_gcur[g] = a; a += d_gcount[g]; }
    }
}

__global__ void k_scatter()
{
    __shared__ int cnt[NG], base[NG];
    const int tid = threadIdx.x;
    if (tid < NG) cnt[tid] = 0;
    __syncthreads();
    const int n = blockIdx.x * blockDim.x + tid;
    const int g = d_gsel[n];
    const int rr = atomicAdd(&cnt[g], 1);
    __syncthreads();
    if (tid < NG) base[tid] = atomicAdd(&d_gcur[tid], cnt[tid]);
    __syncthreads();
    d_perm[base[g] + rr] = n;
}

// ============================================================
// Kernel 2: mini-gate GEMM (gathered rows) + top-4 epilogue
// ============================================================
__global__ void __launch_bounds__(256, 2)
k_gemm2(const float* __restrict__ X, float* __restrict__ out)
{
    const int g = blockIdx.y;
    const int cnt = d_gcount[g];
    const int start = blockIdx.x * BM;
    if (start >= cnt) return;
    const int nvalid = min(BM, cnt - start);
    const int off = d_goff[g];

    extern __shared__ __align__(16) char sm[];
    __shared__ int rows_s[BM];
    const int tid = threadIdx.x;
    if (tid < BM) {
        int ix = start + tid;
        if (ix >= cnt) ix = cnt - 1;   // clamp: duplicate rows, discarded
        rows_s[tid] = d_perm[off + ix];
    }
    __syncthreads();

    const char* xs = (const char*)(X + (size_t)rows_s[tid >> 2] * HID) + (tid & 3) * 16;
    const char* whs = (const char*)(d_wmhi + (size_t)g * HID * NE)
                      + (tid >> 2) * 64 + (tid & 3) * 16;
    const char* wls = (const char*)(d_wmlo + (size_t)g * HID * NE)
                      + (tid >> 2) * 64 + (tid & 3) * 16;

    float* red = (float*)sm;
    gemm_core(sm, xs, whs, wls, tid, red);

    float* pb = (float*)(sm + 4608);   // [64][17]
    if (tid < BM) {
        const bool valid = (tid < nvalid);
        float lg[NE];
#pragma unroll
        for (int e = 0; e < NE; e++) lg[e] = red[tid * 17 + e];
        float mx = lg[0];
#pragma unroll
        for (int e = 1; e < NE; e++) mx = fmaxf(mx, lg[e]);
        float ex[NE], ss = 0.f;
#pragma unroll
        for (int e = 0; e < NE; e++) { ex[e] = __expf(lg[e] - mx); ss += ex[e]; }
        const float inv = 1.0f / ss;
#pragma unroll
        for (int e = 0; e < NE; e++) pb[tid * 17 + e] = valid ? ex[e] * inv : 0.f;

        if (valid) {
            // top-4 by logit; strict > keeps lowest index on ties (lax.top_k order)
            float cur[NE];
#pragma unroll
            for (int e = 0; e < NE; e++) cur[e] = lg[e];
            int eidx[4];
            float ev[4], den = 0.f;
#pragma unroll
            for (int j = 0; j < 4; j++) {
                float best = -3.4e38f;
                int bi = 0;
#pragma unroll
                for (int e = 0; e < NE; e++)
                    if (cur[e] > best) { best = cur[e]; bi = e; }
                cur[bi] = -3.4e38f;
                eidx[j] = bi;
                ev[j] = ex[bi];
                den += ex[bi];
            }
            // group prob cancels in normalization: final = ex_j / sum(top4 ex)
            const float invd = 1.0f / den;
            const int n = rows_s[tid];
#pragma unroll
            for (int j = 0; j < 4; j++) {
                out[(size_t)n * 4 + j] = ev[j] * invd;
                out[(size_t)N_TOK * 4 + (size_t)n * 4 + j] = (float)(g * NE + eidx[j]);
            }
        }
    }
    __syncthreads();
    if (tid < NE) {
        float s = 0.f;
        for (int t = 0; t < BM; t++) s += pb[t * 17 + tid];
        atomicAdd(&d_msum[tid], s);
    }
}

// ============================================================
// Finalize: aux loss
// ============================================================
__global__ void k_final(float* __restrict__ out, int out_size)
{
    if (threadIdx.x == 0) {
        float a = 0.f;
        for (int i = 0; i < NG; i++) { float x = d_gsum[i] / (float)N_TOK; a += x * x; }
        for (int i = 0; i < NE; i++) { float x = d_msum[i] / (float)N_TOK; a += x * x; }
        out[out_size - 1] = a;
    }
}

// ============================================================
extern "C" void kernel_launch(void* const* d_in, const int* in_sizes, int n_in,
                              void* d_out, int out_size)
{
    const float* X  = (const float*)d_in[0];  // hidden_states [N, H]
    const float* W1 = (const float*)d_in[1];  // group_gate_w  [16, H]
    const float* WM = (const float*)d_in[2];  // mini_gates    [16, H, 16]
    float* out = (float*)d_out;               // [probs N*4 | indices N*4 | aux]

    cudaFuncSetAttribute(k_gemm1, cudaFuncAttributeMaxDynamicSharedMemorySize, RING_B);
    cudaFuncSetAttribute(k_gemm2, cudaFuncAttributeMaxDynamicSharedMemorySize, RING_B);

    k_prep_w1<<<HID / 256, 256>>>(W1);
    k_prep_wm<<<(NG * HID * NE) / 1024, 256>>>(WM);
    k_gemm1<<<N_TOK / BM, 256, RING_B>>>(X);
    k_prefix<<<1, 32>>>();
    k_scatter<<<N_TOK / 256, 256>>>();
    k_gemm2<<<dim3(N_TOK / BM, NG), 256, RING_B>>>(X, out);
    k_final<<<1, 32>>>(out, out_size);
}

// round 6
// speedup vs baseline: 1.3347x; 1.3347x over previous
#include <cuda_runtime.h>
#include <cstdint>

#define N_TOK 8192
#define HID   8192
#define NG    16
#define NE    16

#define BM      64
#define BK      64
#define NSTAGE  (HID / BK)        // 128
#define NBUF    4

// stage slot: [0,16384) raw X fp32 (64 tok x 256B, chunk-swizzled); [16384, 20480) W bf16 split
#define SLOT_B   20480
#define W_OFF    16384
#define RING_B   (NBUF * SLOT_B)   // 81920 dynamic smem

// W split layout (uint32 words): per stage 1024 words = hi[kp32][n16] (512) + lo (512)
#define WSTG_W   1024

typedef unsigned long long ull;

// ---------------- device scratch ----------------
__device__ uint32_t d_w1s[NSTAGE * WSTG_W];            // 512KB
__device__ uint32_t d_wms[NG * NSTAGE * WSTG_W];       // 8MB
__device__ float d_gsum[NG];
__device__ float d_msum[NE];
__device__ int   d_gsel[N_TOK];
__device__ int   d_gcount[NG];
__device__ int   d_goff[NG];
__device__ int   d_gcur[NG];
__device__ int   d_perm[N_TOK];

// ---------------- helpers ----------------
__device__ __forceinline__ uint32_t s2u(const void* p) {
    return (uint32_t)__cvta_generic_to_shared(p);
}
__device__ __forceinline__ void cp16(uint32_t dst, const void* src) {
    asm volatile("cp.async.cg.shared.global [%0], [%1], 16;" :: "r"(dst), "l"(src));
}
#define CP_COMMIT() asm volatile("cp.async.commit_group;" ::: "memory")
#define CP_WAIT2()  asm volatile("cp.async.wait_group 2;" ::: "memory")
#define CP_WAIT0()  asm volatile("cp.async.wait_group 0;" ::: "memory")

// pack two f32 -> bf16x2 (lower = v0, upper = v1)
__device__ __forceinline__ uint32_t pkbf(float v0, float v1) {
    uint32_t d;
    asm("cvt.rn.bf16x2.f32 %0, %1, %2;" : "=r"(d) : "f"(v1), "f"(v0));
    return d;
}
// hi/lo split of an f32 pair into two bf16x2 regs
__device__ __forceinline__ void split2(float v0, float v1, uint32_t& hi, uint32_t& lo) {
    hi = pkbf(v0, v1);
    float h0 = __uint_as_float(hi << 16);
    float h1 = __uint_as_float(hi & 0xFFFF0000u);
    lo = pkbf(v0 - h0, v1 - h1);
}
__device__ __forceinline__ void mma16(float* d, const uint32_t* a, uint32_t b0, uint32_t b1) {
    asm volatile(
        "mma.sync.aligned.m16n8k16.row.col.f32.bf16.bf16.f32 "
        "{%0,%1,%2,%3}, {%4,%5,%6,%7}, {%8,%9}, {%0,%1,%2,%3};"
        : "+f"(d[0]), "+f"(d[1]), "+f"(d[2]), "+f"(d[3])
        : "r"(a[0]), "r"(a[1]), "r"(a[2]), "r"(a[3]), "r"(b0), "r"(b1));
}

// ============================================================
// Prep: split weights into fragment-ready packed bf16x2 hi/lo
// word(s, kp, n) = {bf16(W[n][s*64+2kp]), bf16(W[n][s*64+2kp+1])}
// ============================================================
__global__ void k_prep_w1(const float* __restrict__ W1)
{
    const int idx = blockIdx.x * 256 + threadIdx.x;    // 256 blocks -> 65536
    const int s = idx >> 9, kp = (idx >> 4) & 31, n = idx & 15;
    const int k = s * 64 + kp * 2;
    const float v0 = W1[(size_t)n * HID + k], v1 = W1[(size_t)n * HID + k + 1];
    uint32_t hi, lo;
    split2(v0, v1, hi, lo);
    d_w1s[s * WSTG_W + kp * 16 + n] = hi;
    d_w1s[s * WSTG_W + 512 + kp * 16 + n] = lo;
    if (idx < NG) { d_gsum[idx] = 0.f; d_msum[idx] = 0.f; d_gcount[idx] = 0; }
}

__global__ void k_prep_wm(const float* __restrict__ WM)
{
    const int idx = blockIdx.x * 256 + threadIdx.x;    // 4096 blocks -> 1048576
    const int g = idx >> 16, s = (idx >> 9) & 127, kp = (idx >> 4) & 31, n = idx & 15;
    const int k = s * 64 + kp * 2;
    const float* src = WM + ((size_t)g * HID + k) * NE + n;
    const float v0 = src[0], v1 = src[NE];
    uint32_t hi, lo;
    split2(v0, v1, hi, lo);
    uint32_t* dst = d_wms + (size_t)g * (NSTAGE * WSTG_W) + s * WSTG_W + kp * 16 + n;
    dst[0] = hi;
    dst[512] = lo;
}

// ============================================================
// Core GEMM: C[64 tok x 16] = X . W^T via bf16 HMMA 4-term split.
// Warp w: mt = w&3 (m16 tile), kh = w>>2 (k-half of each 64-k stage).
// Produces red[64][17] (cross-kh reduced) in smem.
// ============================================================
__device__ __forceinline__ void gemm_core(char* sm, const float* xrow_base,
                                          const char* xchunk, const uint32_t* wsplit,
                                          int tid, float* red)
{
    const int w = tid >> 5, lane = tid & 31;
    const int mt = w & 3, kh = w >> 2;
    const int q = lane >> 2, c = lane & 3;
    const uint32_t smb = s2u(sm);

    // ---- loader mapping ----
    // X: thread covers 4 chunks (16B) of row (tid>>2): chunks (tid&3)+4j, j=0..3
    const int lrow = tid >> 2, lc4 = tid & 3;
    const char* xsrc = (const char*)xrow_base;   // row base ptr per-thread (caller adds row)
    uint32_t xdst[4];
    const char* xs[4];
#pragma unroll
    for (int j = 0; j < 4; j++) {
        const int ch = lc4 + 4 * j;
        xdst[j] = smb + lrow * 256 + ((ch ^ ((lrow & 7) << 1)) << 4);
        xs[j] = xchunk + ch * 16;
    }
    const uint32_t wdst = smb + W_OFF + tid * 16;
    const char* wsrc = (const char*)wsplit + tid * 16;

    // ---- A fragment smem offsets: [kk_loc][j] ----
    uint32_t offA[2][4];
#pragma unroll
    for (int kl = 0; kl < 2; kl++) {
        const int kk = kh * 2 + kl;
#pragma unroll
        for (int j = 0; j < 4; j++) {
            const int row = mt * 16 + q + (j & 1) * 8;
            const int kp = kk * 8 + c + (j >> 1) * 4;
            offA[kl][j] = row * 256 + (((kp >> 1) ^ ((row & 7) << 1)) << 4) + (kp & 1) * 8;
        }
    }
    // ---- B fragment smem offsets (hi; lo = +2048): [kk_loc][nt][b01] ----
    uint32_t offB[2][2][2];
#pragma unroll
    for (int kl = 0; kl < 2; kl++) {
        const int kk = kh * 2 + kl;
#pragma unroll
        for (int nt = 0; nt < 2; nt++) {
            const int n = nt * 8 + q;
            offB[kl][nt][0] = W_OFF + ((kk * 8 + c) * 16 + n) * 4;
            offB[kl][nt][1] = W_OFF + ((kk * 8 + c + 4) * 16 + n) * 4;
        }
    }

    float acc[2][4];
#pragma unroll
    for (int nt = 0; nt < 2; nt++)
#pragma unroll
        for (int i = 0; i < 4; i++) acc[nt][i] = 0.f;

#define GISSUE(s_) do {                                            \
        const uint32_t b_ = ((s_) & 3) * SLOT_B;                   \
        const size_t o_ = (size_t)(s_) * 256;                      \
        cp16(xdst[0] + b_, xs[0] + o_);                            \
        cp16(xdst[1] + b_, xs[1] + o_);                            \
        cp16(xdst[2] + b_, xs[2] + o_);                            \
        cp16(xdst[3] + b_, xs[3] + o_);                            \
        cp16(wdst + b_, wsrc + (size_t)(s_) * 4096);               \
    } while (0)

    GISSUE(0); CP_COMMIT();
    GISSUE(1); CP_COMMIT();
    GISSUE(2); CP_COMMIT();

    for (int s = 0; s < NSTAGE; s++) {
        CP_WAIT2();
        __syncthreads();
        if (s + 3 < NSTAGE) GISSUE(s + 3);
        CP_COMMIT();

        const char* bb = sm + (s & 3) * SLOT_B;
#pragma unroll
        for (int kl = 0; kl < 2; kl++) {
            uint32_t ah[4], al[4];
#pragma unroll
            for (int j = 0; j < 4; j++) {
                float2 v = *(const float2*)(bb + offA[kl][j]);
                split2(v.x, v.y, ah[j], al[j]);
            }
#pragma unroll
            for (int nt = 0; nt < 2; nt++) {
                const uint32_t bh0 = *(const uint32_t*)(bb + offB[kl][nt][0]);
                const uint32_t bh1 = *(const uint32_t*)(bb + offB[kl][nt][1]);
                const uint32_t bl0 = *(const uint32_t*)(bb + offB[kl][nt][0] + 2048);
                const uint32_t bl1 = *(const uint32_t*)(bb + offB[kl][nt][1] + 2048);
                mma16(acc[nt], ah, bh0, bh1);
                mma16(acc[nt], ah, bl0, bl1);
                mma16(acc[nt], al, bh0, bh1);
                mma16(acc[nt], al, bl0, bl1);
            }
        }
    }
#undef GISSUE

    CP_WAIT0();            // drain stragglers before smem reuse
    __syncthreads();

    // ---- cross-kh reduction into red[64][17] ----
    // D frag: d0,d1 = C[q][2c,2c+1], d2,d3 = C[q+8][...]; rows + mt*16, cols + nt*8
    for (int step = 0; step < 2; step++) {
        if (kh == step) {
#pragma unroll
            for (int nt = 0; nt < 2; nt++) {
                const int r0 = mt * 16 + q, cc = nt * 8 + 2 * c;
                if (step == 0) {
                    red[r0 * 17 + cc]           = acc[nt][0];
                    red[r0 * 17 + cc + 1]       = acc[nt][1];
                    red[(r0 + 8) * 17 + cc]     = acc[nt][2];
                    red[(r0 + 8) * 17 + cc + 1] = acc[nt][3];
                } else {
                    red[r0 * 17 + cc]           += acc[nt][0];
                    red[r0 * 17 + cc + 1]       += acc[nt][1];
                    red[(r0 + 8) * 17 + cc]     += acc[nt][2];
                    red[(r0 + 8) * 17 + cc + 1] += acc[nt][3];
                }
            }
        }
        __syncthreads();
    }
}

// ============================================================
// Kernel 1: group-gate GEMM + softmax/argmax/sums/hist
// ============================================================
__global__ void __launch_bounds__(256, 2)
k_gemm1(const float* __restrict__ X)
{
    extern __shared__ __align__(16) char sm[];
    __shared__ int shist[NG];
    const int tid = threadIdx.x;
    if (tid < NG) shist[tid] = 0;

    const float* xrow = X + (size_t)(blockIdx.x * BM + (tid >> 2)) * HID;
    float* red = (float*)sm;
    gemm_core(sm, xrow, (const char*)xrow, d_w1s, tid, red);

    float* pb = (float*)(sm + 4608);   // [64][17]
    if (tid < BM) {
        float lg[NG];
#pragma unroll
        for (int g = 0; g < NG; g++) lg[g] = red[tid * 17 + g];
        float mx = lg[0];
        int gi = 0;
#pragma unroll
        for (int g = 1; g < NG; g++)
            if (lg[g] > mx) { mx = lg[g]; gi = g; }
        float p[NG], ss = 0.f;
#pragma unroll
        for (int g = 0; g < NG; g++) { p[g] = __expf(lg[g] - mx); ss += p[g]; }
        const float inv = 1.0f / ss;
#pragma unroll
        for (int g = 0; g < NG; g++) pb[tid * 17 + g] = p[g] * inv;
        d_gsel[blockIdx.x * BM + tid] = gi;
        atomicAdd(&shist[gi], 1);
    }
    __syncthreads();
    if (tid < NG) {
        float s = 0.f;
        for (int t = 0; t < BM; t++) s += pb[t * 17 + tid];
        atomicAdd(&d_gsum[tid], s);
        atomicAdd(&d_gcount[tid], shist[tid]);
    }
}

// ============================================================
// Sorting pipeline
// ============================================================
__global__ void k_prefix()
{
    if (threadIdx.x == 0) {
        int a = 0;
        for (int g = 0; g < NG; g++) { d_goff[g] = a; d_gcur[g] = a; a += d_gcount[g]; }
    }
}

__global__ void k_scatter()
{
    __shared__ int cnt[NG], base[NG];
    const int tid = threadIdx.x;
    if (tid < NG) cnt[tid] = 0;
    __syncthreads();
    const int n = blockIdx.x * blockDim.x + tid;
    const int g = d_gsel[n];
    const int rr = atomicAdd(&cnt[g], 1);
    __syncthreads();
    if (tid < NG) base[tid] = atomicAdd(&d_gcur[tid], cnt[tid]);
    __syncthreads();
    d_perm[base[g] + rr] = n;
}

// ============================================================
// Kernel 2: mini-gate GEMM (gathered rows) + top-4 epilogue
// ============================================================
__global__ void __launch_bounds__(256, 2)
k_gemm2(const float* __restrict__ X, float* __restrict__ out)
{
    const int g = blockIdx.y;
    const int cnt = d_gcount[g];
    const int start = blockIdx.x * BM;
    if (start >= cnt) return;
    const int nvalid = min(BM, cnt - start);
    const int off = d_goff[g];

    extern __shared__ __align__(16) char sm[];
    __shared__ int rows_s[BM];
    const int tid = threadIdx.x;
    if (tid < BM) {
        int ix = start + tid;
        if (ix >= cnt) ix = cnt - 1;   // clamp: duplicate rows, discarded
        rows_s[tid] = d_perm[off + ix];
    }
    __syncthreads();

    const float* xrow = X + (size_t)rows_s[tid >> 2] * HID;
    const uint32_t* wsp = d_wms + (size_t)g * (NSTAGE * WSTG_W);
    float* red = (float*)sm;
    gemm_core(sm, xrow, (const char*)xrow, wsp, tid, red);

    float* pb = (float*)(sm + 4608);   // [64][17]
    if (tid < BM) {
        const bool valid = (tid < nvalid);
        float lg[NE];
#pragma unroll
        for (int e = 0; e < NE; e++) lg[e] = red[tid * 17 + e];
        float mx = lg[0];
#pragma unroll
        for (int e = 1; e < NE; e++) mx = fmaxf(mx, lg[e]);
        float ex[NE], ss = 0.f;
#pragma unroll
        for (int e = 0; e < NE; e++) { ex[e] = __expf(lg[e] - mx); ss += ex[e]; }
        const float inv = 1.0f / ss;
#pragma unroll
        for (int e = 0; e < NE; e++) pb[tid * 17 + e] = valid ? ex[e] * inv : 0.f;

        if (valid) {
            // top-4 by logit; strict > keeps lowest index on ties (lax.top_k order)
            float cur[NE];
#pragma unroll
            for (int e = 0; e < NE; e++) cur[e] = lg[e];
            int eidx[4];
            float ev[4], den = 0.f;
#pragma unroll
            for (int j = 0; j < 4; j++) {
                float best = -3.4e38f;
                int bi = 0;
#pragma unroll
                for (int e = 0; e < NE; e++)
                    if (cur[e] > best) { best = cur[e]; bi = e; }
                cur[bi] = -3.4e38f;
                eidx[j] = bi;
                ev[j] = ex[bi];
                den += ex[bi];
            }
            // group prob cancels in normalization: final = ex_j / sum(top4 ex)
            const float invd = 1.0f / den;
            const int n = rows_s[tid];
#pragma unroll
            for (int j = 0; j < 4; j++) {
                out[(size_t)n * 4 + j] = ev[j] * invd;
                out[(size_t)N_TOK * 4 + (size_t)n * 4 + j] = (float)(g * NE + eidx[j]);
            }
        }
    }
    __syncthreads();
    if (tid < NE) {
        float s = 0.f;
        for (int t = 0; t < BM; t++) s += pb[t * 17 + tid];
        atomicAdd(&d_msum[tid], s);
    }
}

// ============================================================
// Finalize: aux loss
// ============================================================
__global__ void k_final(float* __restrict__ out, int out_size)
{
    if (threadIdx.x == 0) {
        float a = 0.f;
        for (int i = 0; i < NG; i++) { float x = d_gsum[i] / (float)N_TOK; a += x * x; }
        for (int i = 0; i < NE; i++) { float x = d_msum[i] / (float)N_TOK; a += x * x; }
        out[out_size - 1] = a;
    }
}

// ============================================================
extern "C" void kernel_launch(void* const* d_in, const int* in_sizes, int n_in,
                              void* d_out, int out_size)
{
    const float* X  = (const float*)d_in[0];  // hidden_states [N, H]
    const float* W1 = (const float*)d_in[1];  // group_gate_w  [16, H]
    const float* WM = (const float*)d_in[2];  // mini_gates    [16, H, 16]
    float* out = (float*)d_out;               // [probs N*4 | indices N*4 | aux]

    cudaFuncSetAttribute(k_gemm1, cudaFuncAttributeMaxDynamicSharedMemorySize, RING_B);
    cudaFuncSetAttribute(k_gemm2, cudaFuncAttributeMaxDynamicSharedMemorySize, RING_B);

    k_prep_w1<<<256, 256>>>(W1);
    k_prep_wm<<<4096, 256>>>(WM);
    k_gemm1<<<N_TOK / BM, 256, RING_B>>>(X);
    k_prefix<<<1, 32>>>();
    k_scatter<<<N_TOK / 256, 256>>>();
    k_gemm2<<<dim3(N_TOK / BM, NG), 256, RING_B>>>(X, out);
    k_final<<<1, 32>>>(out, out_size);
}

// round 7
// speedup vs baseline: 1.6797x; 1.2585x over previous
#include <cuda_runtime.h>
#include <cstdint>

#define N_TOK 8192
#define HID   8192
#define NG    16
#define NE    16

#define BM      64
#define BK      64
#define NSTAGE  (HID / BK)        // 128
#define NBUF    8
#define DEPTH   6

// stage slot: [0,16384) raw X fp32 (64 tok x 256B, chunk-swizzled); [16384, 20480) W bf16 split
#define SLOT_B   20480
#define W_OFF    16384
#define RING_B   (NBUF * SLOT_B)   // 163840 dynamic smem

// W split layout (uint32 words): per stage 1024 words = hi[kp32][n16] (512) + lo (512)
#define WSTG_W   1024

typedef unsigned long long ull;

// ---------------- device scratch ----------------
__device__ uint32_t d_w1s[NSTAGE * WSTG_W];            // 512KB
__device__ uint32_t d_wms[NG * NSTAGE * WSTG_W];       // 8MB
__device__ float d_gsum[NG];
__device__ float d_msum[NE];
__device__ int   d_gsel[N_TOK];
__device__ int   d_gcount[NG];
__device__ int   d_gcur[NG];
__device__ int   d_perm[N_TOK];

// ---------------- helpers ----------------
__device__ __forceinline__ uint32_t s2u(const void* p) {
    return (uint32_t)__cvta_generic_to_shared(p);
}
__device__ __forceinline__ void cp16(uint32_t dst, const void* src) {
    asm volatile("cp.async.cg.shared.global [%0], [%1], 16;" :: "r"(dst), "l"(src));
}
#define CP_COMMIT() asm volatile("cp.async.commit_group;" ::: "memory")
#define CP_WAIT5()  asm volatile("cp.async.wait_group 5;" ::: "memory")
#define CP_WAIT0()  asm volatile("cp.async.wait_group 0;" ::: "memory")

// pack two f32 -> bf16x2 (lower = v0, upper = v1)
__device__ __forceinline__ uint32_t pkbf(float v0, float v1) {
    uint32_t d;
    asm("cvt.rn.bf16x2.f32 %0, %1, %2;" : "=r"(d) : "f"(v1), "f"(v0));
    return d;
}
// hi/lo split of an f32 pair into two bf16x2 regs
__device__ __forceinline__ void split2(float v0, float v1, uint32_t& hi, uint32_t& lo) {
    hi = pkbf(v0, v1);
    float h0 = __uint_as_float(hi << 16);
    float h1 = __uint_as_float(hi & 0xFFFF0000u);
    lo = pkbf(v0 - h0, v1 - h1);
}
__device__ __forceinline__ void mma16(float* d, const uint32_t* a, uint32_t b0, uint32_t b1) {
    asm volatile(
        "mma.sync.aligned.m16n8k16.row.col.f32.bf16.bf16.f32 "
        "{%0,%1,%2,%3}, {%4,%5,%6,%7}, {%8,%9}, {%0,%1,%2,%3};"
        : "+f"(d[0]), "+f"(d[1]), "+f"(d[2]), "+f"(d[3])
        : "r"(a[0]), "r"(a[1]), "r"(a[2]), "r"(a[3]), "r"(b0), "r"(b1));
}

// ============================================================
// Prep (fused): split W1 and WM into fragment-ready packed bf16x2 hi/lo.
// Blocks [0,4096): WM; blocks [4096,4352): W1 (+ zero scalars in blk 4096).
// word(s, kp, n) = {bf16(W[n][s*64+2kp]), bf16(W[n][s*64+2kp+1])}
// ============================================================
__global__ void k_prep(const float* __restrict__ W1, const float* __restrict__ WM)
{
    if (blockIdx.x < 4096) {
        const int idx = blockIdx.x * 256 + threadIdx.x;    // -> 1048576
        const int g = idx >> 16, s = (idx >> 9) & 127, kp = (idx >> 4) & 31, n = idx & 15;
        const int k = s * 64 + kp * 2;
        const float* src = WM + ((size_t)g * HID + k) * NE + n;
        const float v0 = src[0], v1 = src[NE];
        uint32_t hi, lo;
        split2(v0, v1, hi, lo);
        uint32_t* dst = d_wms + (size_t)g * (NSTAGE * WSTG_W) + s * WSTG_W + kp * 16 + n;
        dst[0] = hi;
        dst[512] = lo;
    } else {
        const int idx = (blockIdx.x - 4096) * 256 + threadIdx.x;   // -> 65536
        const int s = idx >> 9, kp = (idx >> 4) & 31, n = idx & 15;
        const int k = s * 64 + kp * 2;
        const float v0 = W1[(size_t)n * HID + k], v1 = W1[(size_t)n * HID + k + 1];
        uint32_t hi, lo;
        split2(v0, v1, hi, lo);
        d_w1s[s * WSTG_W + kp * 16 + n] = hi;
        d_w1s[s * WSTG_W + 512 + kp * 16 + n] = lo;
        if (idx < NG) {
            d_gsum[idx] = 0.f;
            d_msum[idx] = 0.f;
            d_gcount[idx] = 0;
            d_gcur[idx] = 0;
        }
    }
}

// ============================================================
// Core GEMM: C[64 tok x 16] = X . W^T via bf16 HMMA 4-term split.
// Warp w: mt = w&3 (m16 tile), kh = w>>2 (k-half of each 64-k stage).
// Produces red[64][17] (cross-kh reduced) in smem.
// ============================================================
__device__ __forceinline__ void gemm_core(char* sm, const char* xchunk,
                                          const uint32_t* wsplit,
                                          int tid, float* red)
{
    const int w = tid >> 5, lane = tid & 31;
    const int mt = w & 3, kh = w >> 2;
    const int q = lane >> 2, c = lane & 3;
    const uint32_t smb = s2u(sm);

    // ---- loader mapping ----
    const int lrow = tid >> 2, lc4 = tid & 3;
    uint32_t xdst[4];
    const char* xs[4];
#pragma unroll
    for (int j = 0; j < 4; j++) {
        const int ch = lc4 + 4 * j;
        xdst[j] = smb + lrow * 256 + ((ch ^ ((lrow & 7) << 1)) << 4);
        xs[j] = xchunk + ch * 16;
    }
    const uint32_t wdst = smb + W_OFF + tid * 16;
    const char* wsrc = (const char*)wsplit + tid * 16;

    // ---- A fragment smem offsets: [kk_loc][j] ----
    uint32_t offA[2][4];
#pragma unroll
    for (int kl = 0; kl < 2; kl++) {
        const int kk = kh * 2 + kl;
#pragma unroll
        for (int j = 0; j < 4; j++) {
            const int row = mt * 16 + q + (j & 1) * 8;
            const int kp = kk * 8 + c + (j >> 1) * 4;
            offA[kl][j] = row * 256 + (((kp >> 1) ^ ((row & 7) << 1)) << 4) + (kp & 1) * 8;
        }
    }
    // ---- B fragment smem offsets (hi; lo = +2048): [kk_loc][nt][b01] ----
    uint32_t offB[2][2][2];
#pragma unroll
    for (int kl = 0; kl < 2; kl++) {
        const int kk = kh * 2 + kl;
#pragma unroll
        for (int nt = 0; nt < 2; nt++) {
            const int n = nt * 8 + q;
            offB[kl][nt][0] = W_OFF + ((kk * 8 + c) * 16 + n) * 4;
            offB[kl][nt][1] = W_OFF + ((kk * 8 + c + 4) * 16 + n) * 4;
        }
    }

    float acc[2][4];
#pragma unroll
    for (int nt = 0; nt < 2; nt++)
#pragma unroll
        for (int i = 0; i < 4; i++) acc[nt][i] = 0.f;

#define GISSUE(s_) do {                                            \
        const uint32_t b_ = ((s_) & 7) * SLOT_B;                   \
        const size_t o_ = (size_t)(s_) * 256;                      \
        cp16(xdst[0] + b_, xs[0] + o_);                            \
        cp16(xdst[1] + b_, xs[1] + o_);                            \
        cp16(xdst[2] + b_, xs[2] + o_);                            \
        cp16(xdst[3] + b_, xs[3] + o_);                            \
        cp16(wdst + b_, wsrc + (size_t)(s_) * 4096);               \
    } while (0)

#pragma unroll
    for (int p = 0; p < DEPTH; p++) { GISSUE(p); CP_COMMIT(); }

    for (int s = 0; s < NSTAGE; s++) {
        CP_WAIT5();
        __syncthreads();
        if (s + DEPTH < NSTAGE) GISSUE(s + DEPTH);
        CP_COMMIT();

        const char* bb = sm + (s & 7) * SLOT_B;
#pragma unroll
        for (int kl = 0; kl < 2; kl++) {
            uint32_t ah[4], al[4];
#pragma unroll
            for (int j = 0; j < 4; j++) {
                float2 v = *(const float2*)(bb + offA[kl][j]);
                split2(v.x, v.y, ah[j], al[j]);
            }
#pragma unroll
            for (int nt = 0; nt < 2; nt++) {
                const uint32_t bh0 = *(const uint32_t*)(bb + offB[kl][nt][0]);
                const uint32_t bh1 = *(const uint32_t*)(bb + offB[kl][nt][1]);
                const uint32_t bl0 = *(const uint32_t*)(bb + offB[kl][nt][0] + 2048);
                const uint32_t bl1 = *(const uint32_t*)(bb + offB[kl][nt][1] + 2048);
                mma16(acc[nt], ah, bh0, bh1);
                mma16(acc[nt], ah, bl0, bl1);
                mma16(acc[nt], al, bh0, bh1);
                mma16(acc[nt], al, bl0, bl1);
            }
        }
    }
#undef GISSUE

    CP_WAIT0();            // drain stragglers before smem reuse
    __syncthreads();

    // ---- cross-kh reduction into red[64][17] ----
    for (int step = 0; step < 2; step++) {
        if (kh == step) {
#pragma unroll
            for (int nt = 0; nt < 2; nt++) {
                const int r0 = mt * 16 + q, cc = nt * 8 + 2 * c;
                if (step == 0) {
                    red[r0 * 17 + cc]           = acc[nt][0];
                    red[r0 * 17 + cc + 1]       = acc[nt][1];
                    red[(r0 + 8) * 17 + cc]     = acc[nt][2];
                    red[(r0 + 8) * 17 + cc + 1] = acc[nt][3];
                } else {
                    red[r0 * 17 + cc]           += acc[nt][0];
                    red[r0 * 17 + cc + 1]       += acc[nt][1];
                    red[(r0 + 8) * 17 + cc]     += acc[nt][2];
                    red[(r0 + 8) * 17 + cc + 1] += acc[nt][3];
                }
            }
        }
        __syncthreads();
    }
}

// ============================================================
// Kernel 1: group-gate GEMM + softmax/argmax/sums/hist
// ============================================================
__global__ void __launch_bounds__(256, 1)
k_gemm1(const float* __restrict__ X)
{
    extern __shared__ __align__(16) char sm[];
    __shared__ int shist[NG];
    const int tid = threadIdx.x;
    if (tid < NG) shist[tid] = 0;

    const float* xrow = X + (size_t)(blockIdx.x * BM + (tid >> 2)) * HID;
    float* red = (float*)sm;
    gemm_core(sm, (const char*)xrow, d_w1s, tid, red);

    float* pb = (float*)(sm + 4608);   // [64][17]
    if (tid < BM) {
        float lg[NG];
#pragma unroll
        for (int g = 0; g < NG; g++) lg[g] = red[tid * 17 + g];
        float mx = lg[0];
        int gi = 0;
#pragma unroll
        for (int g = 1; g < NG; g++)
            if (lg[g] > mx) { mx = lg[g]; gi = g; }
        float p[NG], ss = 0.f;
#pragma unroll
        for (int g = 0; g < NG; g++) { p[g] = __expf(lg[g] - mx); ss += p[g]; }
        const float inv = 1.0f / ss;
#pragma unroll
        for (int g = 0; g < NG; g++) pb[tid * 17 + g] = p[g] * inv;
        d_gsel[blockIdx.x * BM + tid] = gi;
        atomicAdd(&shist[gi], 1);
    }
    __syncthreads();
    if (tid < NG) {
        float s = 0.f;
        for (int t = 0; t < BM; t++) s += pb[t * 17 + tid];
        atomicAdd(&d_gsum[tid], s);
        atomicAdd(&d_gcount[tid], shist[tid]);
    }
}

// ============================================================
// Scatter with local prefix (k_prefix eliminated)
// ============================================================
__global__ void k_scatter()
{
    __shared__ int cnt[NG], base[NG];
    const int tid = threadIdx.x;
    if (tid < NG) cnt[tid] = 0;
    __syncthreads();
    const int n = blockIdx.x * blockDim.x + tid;
    const int g = d_gsel[n];
    const int rr = atomicAdd(&cnt[g], 1);
    __syncthreads();
    if (tid < NG) {
        int goff = 0;
        for (int h = 0; h < NG; h++) {
            int c = d_gcount[h];
            if (h < tid) goff += c;
        }
        base[tid] = goff + atomicAdd(&d_gcur[tid], cnt[tid]);
    }
    __syncthreads();
    d_perm[base[g] + rr] = n;
}

// ============================================================
// Kernel 2: mini-gate GEMM (gathered rows) + top-4 epilogue
// ============================================================
__global__ void __launch_bounds__(256, 1)
k_gemm2(const float* __restrict__ X, float* __restrict__ out)
{
    const int g = blockIdx.y;
    const int cnt = d_gcount[g];
    const int start = blockIdx.x * BM;
    if (start >= cnt) return;
    const int nvalid = min(BM, cnt - start);

    extern __shared__ __align__(16) char sm[];
    __shared__ int rows_s[BM];
    const int tid = threadIdx.x;
    if (tid == 0) {           // local prefix: offset of group g
        int off = 0;
        for (int h = 0; h < NG; h++) {
            int c = d_gcount[h];
            if (h < g) off += c;
        }
        rows_s[0] = off;      // temp
    }
    __syncthreads();
    const int off = rows_s[0];
    __syncthreads();
    if (tid < BM) {
        int ix = start + tid;
        if (ix >= cnt) ix = cnt - 1;   // clamp: duplicate rows, discarded
        rows_s[tid] = d_perm[off + ix];
    }
    __syncthreads();

    const float* xrow = X + (size_t)rows_s[tid >> 2] * HID;
    const uint32_t* wsp = d_wms + (size_t)g * (NSTAGE * WSTG_W);
    float* red = (float*)sm;
    gemm_core(sm, (const char*)xrow, wsp, tid, red);

    float* pb = (float*)(sm + 4608);   // [64][17]
    if (tid < BM) {
        const bool valid = (tid < nvalid);
        float lg[NE];
#pragma unroll
        for (int e = 0; e < NE; e++) lg[e] = red[tid * 17 + e];
        float mx = lg[0];
#pragma unroll
        for (int e = 1; e < NE; e++) mx = fmaxf(mx, lg[e]);
        float ex[NE], ss = 0.f;
#pragma unroll
        for (int e = 0; e < NE; e++) { ex[e] = __expf(lg[e] - mx); ss += ex[e]; }
        const float inv = 1.0f / ss;
#pragma unroll
        for (int e = 0; e < NE; e++) pb[tid * 17 + e] = valid ? ex[e] * inv : 0.f;

        if (valid) {
            // top-4 by logit; strict > keeps lowest index on ties (lax.top_k order)
            float cur[NE];
#pragma unroll
            for (int e = 0; e < NE; e++) cur[e] = lg[e];
            int eidx[4];
            float ev[4], den = 0.f;
#pragma unroll
            for (int j = 0; j < 4; j++) {
                float best = -3.4e38f;
                int bi = 0;
#pragma unroll
                for (int e = 0; e < NE; e++)
                    if (cur[e] > best) { best = cur[e]; bi = e; }
                cur[bi] = -3.4e38f;
                eidx[j] = bi;
                ev[j] = ex[bi];
                den += ex[bi];
            }
            // group prob cancels in normalization: final = ex_j / sum(top4 ex)
            const float invd = 1.0f / den;
            const int n = rows_s[tid];
#pragma unroll
            for (int j = 0; j < 4; j++) {
                out[(size_t)n * 4 + j] = ev[j] * invd;
                out[(size_t)N_TOK * 4 + (size_t)n * 4 + j] = (float)(g * NE + eidx[j]);
            }
        }
    }
    __syncthreads();
    if (tid < NE) {
        float s = 0.f;
        for (int t = 0; t < BM; t++) s += pb[t * 17 + tid];
        atomicAdd(&d_msum[tid], s);
    }
}

// ============================================================
// Finalize: aux loss
// ============================================================
__global__ void k_final(float* __restrict__ out, int out_size)
{
    if (threadIdx.x == 0) {
        float a = 0.f;
        for (int i = 0; i < NG; i++) { float x = d_gsum[i] / (float)N_TOK; a += x * x; }
        for (int i = 0; i < NE; i++) { float x = d_msum[i] / (float)N_TOK; a += x * x; }
        out[out_size - 1] = a;
    }
}

// ============================================================
extern "C" void kernel_launch(void* const* d_in, const int* in_sizes, int n_in,
                              void* d_out, int out_size)
{
    const float* X  = (const float*)d_in[0];  // hidden_states [N, H]
    const float* W1 = (const float*)d_in[1];  // group_gate_w  [16, H]
    const float* WM = (const float*)d_in[2];  // mini_gates    [16, H, 16]
    float* out = (float*)d_out;               // [probs N*4 | indices N*4 | aux]

    cudaFuncSetAttribute(k_gemm1, cudaFuncAttributeMaxDynamicSharedMemorySize, RING_B);
    cudaFuncSetAttribute(k_gemm2, cudaFuncAttributeMaxDynamicSharedMemorySize, RING_B);

    k_prep<<<4352, 256>>>(W1, WM);                       // launch 1
    k_gemm1<<<N_TOK / BM, 256, RING_B>>>(X);             // launch 2
    k_scatter<<<N_TOK / 256, 256>>>();                   // launch 3
    k_gemm2<<<dim3(N_TOK / BM, NG), 256, RING_B>>>(X, out);  // launch 4 (ncu slot)
    k_final<<<1, 32>>>(out, out_size);                   // launch 5
}

// round 8
// speedup vs baseline: 1.7006x; 1.0124x over previous
#include <cuda_runtime.h>
#include <cstdint>

#define N_TOK 8192
#define HID   8192
#define NG    16
#define NE    16

#define BM      64
#define NSTAGE  (HID / 64)        // 128
#define NBUF    8
#define DEPTH   7
#define NTHR    512

// stage slot: [0,16384) raw X fp32 (64 tok x 256B, chunk-swizzled); [16384, 20480) W bf16 split
#define SLOT_B   20480
#define W_OFF    16384
#define RING_B   (NBUF * SLOT_B)   // 163840 dynamic smem

// W split layout (uint32 words): per stage 1024 words = hi[kp32][n16] (512) + lo (512)
#define WSTG_W   1024

// ---------------- device scratch ----------------
__device__ uint32_t d_w1s[NSTAGE * WSTG_W];            // 512KB
__device__ uint32_t d_wms[NG * NSTAGE * WSTG_W];       // 8MB
__device__ float d_gsum[NG];
__device__ float d_msum[NE];
__device__ int   d_gsel[N_TOK];
__device__ int   d_gcount[NG];
__device__ int   d_gcur[NG];
__device__ int   d_perm[N_TOK];

// ---------------- helpers ----------------
__device__ __forceinline__ uint32_t s2u(const void* p) {
    return (uint32_t)__cvta_generic_to_shared(p);
}
__device__ __forceinline__ void cp16(uint32_t dst, const void* src) {
    asm volatile("cp.async.cg.shared.global [%0], [%1], 16;" :: "r"(dst), "l"(src));
}
#define CP_COMMIT() asm volatile("cp.async.commit_group;" ::: "memory")
#define CP_WAIT6()  asm volatile("cp.async.wait_group 6;" ::: "memory")
#define CP_WAIT0()  asm volatile("cp.async.wait_group 0;" ::: "memory")

__device__ __forceinline__ uint32_t pkbf(float v0, float v1) {
    uint32_t d;
    asm("cvt.rn.bf16x2.f32 %0, %1, %2;" : "=r"(d) : "f"(v1), "f"(v0));
    return d;
}
__device__ __forceinline__ void split2(float v0, float v1, uint32_t& hi, uint32_t& lo) {
    hi = pkbf(v0, v1);
    float h0 = __uint_as_float(hi << 16);
    float h1 = __uint_as_float(hi & 0xFFFF0000u);
    lo = pkbf(v0 - h0, v1 - h1);
}
__device__ __forceinline__ void mma16(float* d, const uint32_t* a, uint32_t b0, uint32_t b1) {
    asm volatile(
        "mma.sync.aligned.m16n8k16.row.col.f32.bf16.bf16.f32 "
        "{%0,%1,%2,%3}, {%4,%5,%6,%7}, {%8,%9}, {%0,%1,%2,%3};"
        : "+f"(d[0]), "+f"(d[1]), "+f"(d[2]), "+f"(d[3])
        : "r"(a[0]), "r"(a[1]), "r"(a[2]), "r"(a[3]), "r"(b0), "r"(b1));
}

// ============================================================
// Prep (fused): split W1 and WM into fragment-ready packed bf16x2 hi/lo.
// word(s, kp, n) = {bf16(W[n][s*64+2kp]), bf16(W[n][s*64+2kp+1])}
// ============================================================
__global__ void k_prep(const float* __restrict__ W1, const float* __restrict__ WM)
{
    if (blockIdx.x < 4096) {
        const int idx = blockIdx.x * 256 + threadIdx.x;    // -> 1048576
        const int g = idx >> 16, s = (idx >> 9) & 127, kp = (idx >> 4) & 31, n = idx & 15;
        const int k = s * 64 + kp * 2;
        const float* src = WM + ((size_t)g * HID + k) * NE + n;
        const float v0 = src[0], v1 = src[NE];
        uint32_t hi, lo;
        split2(v0, v1, hi, lo);
        uint32_t* dst = d_wms + (size_t)g * (NSTAGE * WSTG_W) + s * WSTG_W + kp * 16 + n;
        dst[0] = hi;
        dst[512] = lo;
    } else {
        const int idx = (blockIdx.x - 4096) * 256 + threadIdx.x;   // -> 65536
        const int s = idx >> 9, kp = (idx >> 4) & 31, n = idx & 15;
        const int k = s * 64 + kp * 2;
        const float v0 = W1[(size_t)n * HID + k], v1 = W1[(size_t)n * HID + k + 1];
        uint32_t hi, lo;
        split2(v0, v1, hi, lo);
        d_w1s[s * WSTG_W + kp * 16 + n] = hi;
        d_w1s[s * WSTG_W + 512 + kp * 16 + n] = lo;
        if (idx < NG) {
            d_gsum[idx] = 0.f;
            d_msum[idx] = 0.f;
            d_gcount[idx] = 0;
            d_gcur[idx] = 0;
        }
    }
}

// ============================================================
// Core GEMM (512 thr): C[64 tok x 16] = X . W^T, bf16 HMMA 4-term split.
// Warp w: mt = w&3 (m16 tile), kh = w>>2 (k16-quarter of each 64-k stage).
// Produces red[64][17] (cross-kh reduced) in smem.
// ============================================================
__device__ __forceinline__ void gemm_core(char* sm, const char* xchunk,
                                          const uint32_t* wsplit,
                                          int tid, float* red)
{
    const int w = tid >> 5, lane = tid & 31;
    const int mt = w & 3, kh = w >> 2;         // kh 0..3
    const int q = lane >> 2, c = lane & 3;
    const uint32_t smb = s2u(sm);

    // ---- loader mapping: X 2 chunks/thread; W by threads < 256 ----
    const int lrow = tid >> 3, lc = tid & 7;
    uint32_t xdst[2];
    const char* xs[2];
#pragma unroll
    for (int j = 0; j < 2; j++) {
        const int ch = lc + 8 * j;
        xdst[j] = smb + lrow * 256 + ((ch ^ ((lrow & 7) << 1)) << 4);
        xs[j] = xchunk + ch * 16;
    }
    const bool wload = (tid < 256);
    const uint32_t wdst = smb + W_OFF + tid * 16;
    const char* wsrc = (const char*)wsplit + tid * 16;

    // ---- A fragment smem offsets: [j] ----
    uint32_t offA[4];
#pragma unroll
    for (int j = 0; j < 4; j++) {
        const int row = mt * 16 + q + (j & 1) * 8;
        const int kp = kh * 8 + c + (j >> 1) * 4;
        offA[j] = row * 256 + (((kp >> 1) ^ ((row & 7) << 1)) << 4) + (kp & 1) * 8;
    }
    // ---- B fragment smem offsets (hi; lo = +2048): [nt][b01] ----
    uint32_t offB[2][2];
#pragma unroll
    for (int nt = 0; nt < 2; nt++) {
        const int n = nt * 8 + q;
        offB[nt][0] = W_OFF + ((kh * 8 + c) * 16 + n) * 4;
        offB[nt][1] = W_OFF + ((kh * 8 + c + 4) * 16 + n) * 4;
    }

    float acc[2][4];
#pragma unroll
    for (int nt = 0; nt < 2; nt++)
#pragma unroll
        for (int i = 0; i < 4; i++) acc[nt][i] = 0.f;

#define GISSUE(s_) do {                                            \
        const uint32_t b_ = ((s_) & 7) * SLOT_B;                   \
        const size_t o_ = (size_t)(s_) * 256;                      \
        cp16(xdst[0] + b_, xs[0] + o_);                            \
        cp16(xdst[1] + b_, xs[1] + o_);                            \
        if (wload) cp16(wdst + b_, wsrc + (size_t)(s_) * 4096);    \
    } while (0)

#pragma unroll
    for (int p = 0; p < DEPTH; p++) { GISSUE(p); CP_COMMIT(); }

    for (int s = 0; s < NSTAGE; s++) {
        CP_WAIT6();
        __syncthreads();
        if (s + DEPTH < NSTAGE) GISSUE(s + DEPTH);
        CP_COMMIT();

        const char* bb = sm + (s & 7) * SLOT_B;
        uint32_t ah[4], al[4];
#pragma unroll
        for (int j = 0; j < 4; j++) {
            float2 v = *(const float2*)(bb + offA[j]);
            split2(v.x, v.y, ah[j], al[j]);
        }
#pragma unroll
        for (int nt = 0; nt < 2; nt++) {
            const uint32_t bh0 = *(const uint32_t*)(bb + offB[nt][0]);
            const uint32_t bh1 = *(const uint32_t*)(bb + offB[nt][1]);
            const uint32_t bl0 = *(const uint32_t*)(bb + offB[nt][0] + 2048);
            const uint32_t bl1 = *(const uint32_t*)(bb + offB[nt][1] + 2048);
            mma16(acc[nt], ah, bh0, bh1);
            mma16(acc[nt], ah, bl0, bl1);
            mma16(acc[nt], al, bh0, bh1);
            mma16(acc[nt], al, bl0, bl1);
        }
    }
#undef GISSUE

    CP_WAIT0();            // drain stragglers before smem reuse
    __syncthreads();

    // ---- cross-kh reduction (4 slices) into red[64][17] ----
    for (int step = 0; step < 4; step++) {
        if (kh == step) {
#pragma unroll
            for (int nt = 0; nt < 2; nt++) {
                const int r0 = mt * 16 + q, cc = nt * 8 + 2 * c;
                if (step == 0) {
                    red[r0 * 17 + cc]           = acc[nt][0];
                    red[r0 * 17 + cc + 1]       = acc[nt][1];
                    red[(r0 + 8) * 17 + cc]     = acc[nt][2];
                    red[(r0 + 8) * 17 + cc + 1] = acc[nt][3];
                } else {
                    red[r0 * 17 + cc]           += acc[nt][0];
                    red[r0 * 17 + cc + 1]       += acc[nt][1];
                    red[(r0 + 8) * 17 + cc]     += acc[nt][2];
                    red[(r0 + 8) * 17 + cc + 1] += acc[nt][3];
                }
            }
        }
        __syncthreads();
    }
}

// ============================================================
// Kernel 1: group-gate GEMM + softmax/argmax/sums/hist
// ============================================================
__global__ void __launch_bounds__(NTHR, 1)
k_gemm1(const float* __restrict__ X)
{
    extern __shared__ __align__(16) char sm[];
    __shared__ int shist[NG];
    const int tid = threadIdx.x;
    if (tid < NG) shist[tid] = 0;

    const float* xrow = X + (size_t)(blockIdx.x * BM + (tid >> 3)) * HID;
    float* red = (float*)sm;
    gemm_core(sm, (const char*)xrow, d_w1s, tid, red);

    float* pb = (float*)(sm + 4608);   // [64][17]
    if (tid < BM) {
        float lg[NG];
#pragma unroll
        for (int g = 0; g < NG; g++) lg[g] = red[tid * 17 + g];
        float mx = lg[0];
        int gi = 0;
#pragma unroll
        for (int g = 1; g < NG; g++)
            if (lg[g] > mx) { mx = lg[g]; gi = g; }
        float p[NG], ss = 0.f;
#pragma unroll
        for (int g = 0; g < NG; g++) { p[g] = __expf(lg[g] - mx); ss += p[g]; }
        const float inv = 1.0f / ss;
#pragma unroll
        for (int g = 0; g < NG; g++) pb[tid * 17 + g] = p[g] * inv;
        d_gsel[blockIdx.x * BM + tid] = gi;
        atomicAdd(&shist[gi], 1);
    }
    __syncthreads();
    if (tid < NG) {
        float s = 0.f;
        for (int t = 0; t < BM; t++) s += pb[t * 17 + tid];
        atomicAdd(&d_gsum[tid], s);
        atomicAdd(&d_gcount[tid], shist[tid]);
    }
}

// ============================================================
// Scatter with local prefix
// ============================================================
__global__ void k_scatter()
{
    __shared__ int cnt[NG], base[NG];
    const int tid = threadIdx.x;
    if (tid < NG) cnt[tid] = 0;
    __syncthreads();
    const int n = blockIdx.x * blockDim.x + tid;
    const int g = d_gsel[n];
    const int rr = atomicAdd(&cnt[g], 1);
    __syncthreads();
    if (tid < NG) {
        int goff = 0;
        for (int h = 0; h < NG; h++) {
            int c = d_gcount[h];
            if (h < tid) goff += c;
        }
        base[tid] = goff + atomicAdd(&d_gcur[tid], cnt[tid]);
    }
    __syncthreads();
    d_perm[base[g] + rr] = n;
}

// ============================================================
// Kernel 2: mini-gate GEMM (gathered rows) + top-4 epilogue
// ============================================================
__global__ void __launch_bounds__(NTHR, 1)
k_gemm2(const float* __restrict__ X, float* __restrict__ out)
{
    const int g = blockIdx.y;
    const int cnt = d_gcount[g];
    const int start = blockIdx.x * BM;
    if (start >= cnt) return;
    const int nvalid = min(BM, cnt - start);

    extern __shared__ __align__(16) char sm[];
    __shared__ int rows_s[BM];
    const int tid = threadIdx.x;
    if (tid == 0) {            // local prefix: offset of group g
        int off = 0;
        for (int h = 0; h < NG; h++) {
            int c = d_gcount[h];
            if (h < g) off += c;
        }
        rows_s[0] = off;       // temp
    }
    __syncthreads();
    const int off = rows_s[0];
    __syncthreads();
    if (tid < BM) {
        int ix = start + tid;
        if (ix >= cnt) ix = cnt - 1;   // clamp: duplicate rows, discarded
        rows_s[tid] = d_perm[off + ix];
    }
    __syncthreads();

    const float* xrow = X + (size_t)rows_s[tid >> 3] * HID;
    const uint32_t* wsp = d_wms + (size_t)g * (NSTAGE * WSTG_W);
    float* red = (float*)sm;
    gemm_core(sm, (const char*)xrow, wsp, tid, red);

    float* pb = (float*)(sm + 4608);   // [64][17]
    if (tid < BM) {
        const bool valid = (tid < nvalid);
        float lg[NE];
#pragma unroll
        for (int e = 0; e < NE; e++) lg[e] = red[tid * 17 + e];
        float mx = lg[0];
#pragma unroll
        for (int e = 1; e < NE; e++) mx = fmaxf(mx, lg[e]);
        float ex[NE], ss = 0.f;
#pragma unroll
        for (int e = 0; e < NE; e++) { ex[e] = __expf(lg[e] - mx); ss += ex[e]; }
        const float inv = 1.0f / ss;
#pragma unroll
        for (int e = 0; e < NE; e++) pb[tid * 17 + e] = valid ? ex[e] * inv : 0.f;

        if (valid) {
            // top-4 by logit; strict > keeps lowest index on ties (lax.top_k order)
            float cur[NE];
#pragma unroll
            for (int e = 0; e < NE; e++) cur[e] = lg[e];
            int eidx[4];
            float ev[4], den = 0.f;
#pragma unroll
            for (int j = 0; j < 4; j++) {
                float best = -3.4e38f;
                int bi = 0;
#pragma unroll
                for (int e = 0; e < NE; e++)
                    if (cur[e] > best) { best = cur[e]; bi = e; }
                cur[bi] = -3.4e38f;
                eidx[j] = bi;
                ev[j] = ex[bi];
                den += ex[bi];
            }
            // group prob cancels in normalization: final = ex_j / sum(top4 ex)
            const float invd = 1.0f / den;
            const int n = rows_s[tid];
#pragma unroll
            for (int j = 0; j < 4; j++) {
                out[(size_t)n * 4 + j] = ev[j] * invd;
                out[(size_t)N_TOK * 4 + (size_t)n * 4 + j] = (float)(g * NE + eidx[j]);
            }
        }
    }
    __syncthreads();
    if (tid < NE) {
        float s = 0.f;
        for (int t = 0; t < BM; t++) s += pb[t * 17 + tid];
        atomicAdd(&d_msum[tid], s);
    }
}

// ============================================================
// Finalize: aux loss
// ============================================================
__global__ void k_final(float* __restrict__ out, int out_size)
{
    if (threadIdx.x == 0) {
        float a = 0.f;
        for (int i = 0; i < NG; i++) { float x = d_gsum[i] / (float)N_TOK; a += x * x; }
        for (int i = 0; i < NE; i++) { float x = d_msum[i] / (float)N_TOK; a += x * x; }
        out[out_size - 1] = a;
    }
}

// ============================================================
extern "C" void kernel_launch(void* const* d_in, const int* in_sizes, int n_in,
                              void* d_out, int out_size)
{
    const float* X  = (const float*)d_in[0];  // hidden_states [N, H]
    const float* W1 = (const float*)d_in[1];  // group_gate_w  [16, H]
    const float* WM = (const float*)d_in[2];  // mini_gates    [16, H, 16]
    float* out = (float*)d_out;               // [probs N*4 | indices N*4 | aux]

    cudaFuncSetAttribute(k_gemm1, cudaFuncAttributeMaxDynamicSharedMemorySize, RING_B);
    cudaFuncSetAttribute(k_gemm2, cudaFuncAttributeMaxDynamicSharedMemorySize, RING_B);

    k_prep<<<4352, 256>>>(W1, WM);                            // launch 1
    k_gemm1<<<N_TOK / BM, NTHR, RING_B>>>(X);                 // launch 2
    k_scatter<<<N_TOK / 256, 256>>>();                        // launch 3
    k_gemm2<<<dim3(N_TOK / BM, NG), NTHR, RING_B>>>(X, out);  // launch 4 (ncu slot)
    k_final<<<1, 32>>>(out, out_size);                        // launch 5
}

// round 10
// speedup vs baseline: 1.7881x; 1.0515x over previous
#include <cuda_runtime.h>
#include <cstdint>

#define N_TOK 8192
#define HID   8192
#define NG    16
#define NE    16

#define BM     64
#define NTHR   512
#define NSUP   32                 // superstages of 256 k
#define XROW_B 1056               // padded X row stride (word off ≡ 8 mod 32)
#define W_OFF  (64 * XROW_B)      // 67584
#define WSUP_B 24576              // W bytes per superstage (4 x 6144)
#define SLOT_B (W_OFF + WSUP_B)   // 92160
#define SMEM_DYN (2 * SLOT_B)     // 184320
#define TXB    (64 * 1024 + WSUP_B)  // 90112
#define WSTG_W 1536               // W words per 64-k block (hi 768 + lo 768, rows padded to 24)

typedef unsigned long long ull;

// ---------------- device scratch ----------------
__device__ uint32_t d_w1s[128 * WSTG_W];           // 768KB
__device__ uint32_t d_wms[NG * 128 * WSTG_W];      // 12MB
__device__ float d_gsum[NG];
__device__ float d_msum[NE];
__device__ int   d_gsel[N_TOK];
__device__ int   d_gcount[NG];
__device__ int   d_gcur[NG];
__device__ int   d_perm[N_TOK];

// ---------------- helpers ----------------
__device__ __forceinline__ uint32_t s2u(const void* p) {
    return (uint32_t)__cvta_generic_to_shared(p);
}
__device__ __forceinline__ void bulkcp(uint32_t dst, const void* src, uint32_t n, uint32_t mbar) {
    asm volatile(
        "cp.async.bulk.shared::cluster.global.mbarrier::complete_tx::bytes [%0], [%1], %2, [%3];"
        :: "r"(dst), "l"(src), "r"(n), "r"(mbar) : "memory");
}
#define MB_INIT(a, c) asm volatile("mbarrier.init.shared.b64 [%0], %1;" :: "r"(a), "r"(c) : "memory")
#define MB_EXPECT(a, tx) asm volatile("mbarrier.arrive.expect_tx.shared.b64 _, [%0], %1;" :: "r"(a), "r"(tx) : "memory")
__device__ __forceinline__ void mb_wait(uint32_t mb, uint32_t parity) {
    asm volatile(
        "{\n\t.reg .pred P;\n\t"
        "WL_%=:\n\t"
        "mbarrier.try_wait.parity.acquire.cta.shared::cta.b64 P, [%0], %1, 0x989680;\n\t"
        "@P bra.uni WD_%=;\n\t"
        "bra.uni WL_%=;\n\t"
        "WD_%=:\n\t}"
        :: "r"(mb), "r"(parity) : "memory");
}
__device__ __forceinline__ uint32_t pkbf(float v0, float v1) {
    uint32_t d;
    asm("cvt.rn.bf16x2.f32 %0, %1, %2;" : "=r"(d) : "f"(v1), "f"(v0));
    return d;
}
__device__ __forceinline__ void split2(float v0, float v1, uint32_t& hi, uint32_t& lo) {
    hi = pkbf(v0, v1);
    float h0 = __uint_as_float(hi << 16);
    float h1 = __uint_as_float(hi & 0xFFFF0000u);
    lo = pkbf(v0 - h0, v1 - h1);
}
__device__ __forceinline__ void mma16(float* d, const uint32_t* a, uint32_t b0, uint32_t b1) {
    asm volatile(
        "mma.sync.aligned.m16n8k16.row.col.f32.bf16.bf16.f32 "
        "{%0,%1,%2,%3}, {%4,%5,%6,%7}, {%8,%9}, {%0,%1,%2,%3};"
        : "+f"(d[0]), "+f"(d[1]), "+f"(d[2]), "+f"(d[3])
        : "r"(a[0]), "r"(a[1]), "r"(a[2]), "r"(a[3]), "r"(b0), "r"(b1));
}

// ============================================================
// Prep (fused): split W1/WM -> packed bf16x2 hi/lo, rows padded to 24 words.
// hi word(s, kp, n) at [s*1536 + kp*24 + n]; lo at +768.
// ============================================================
__global__ void k_prep(const float* __restrict__ W1, const float* __restrict__ WM)
{
    if (blockIdx.x < 4096) {
        const int idx = blockIdx.x * 256 + threadIdx.x;    // -> 1048576
        const int g = idx >> 16, s = (idx >> 9) & 127, kp = (idx >> 4) & 31, n = idx & 15;
        const float* src = WM + ((size_t)(g * HID) + s * 64 + kp * 2) * NE + n;
        uint32_t hi, lo;
        split2(src[0], src[NE], hi, lo);
        uint32_t* dst = d_wms + (size_t)g * (128 * WSTG_W) + s * WSTG_W + kp * 24 + n;
        dst[0] = hi;
        dst[768] = lo;
    } else {
        const int idx = (blockIdx.x - 4096) * 256 + threadIdx.x;   // -> 65536
        const int s = idx >> 9, kp = (idx >> 4) & 31, n = idx & 15;
        const int k = s * 64 + kp * 2;
        uint32_t hi, lo;
        split2(W1[(size_t)n * HID + k], W1[(size_t)n * HID + k + 1], hi, lo);
        d_w1s[s * WSTG_W + kp * 24 + n] = hi;
        d_w1s[s * WSTG_W + 768 + kp * 24 + n] = lo;
        if (idx < NG) {
            d_gsum[idx] = 0.f;
            d_msum[idx] = 0.f;
            d_gcount[idx] = 0;
            d_gcur[idx] = 0;
        }
    }
}

// ============================================================
// Core GEMM: C[64 tok x 16] = X . W^T, bf16 HMMA 3-term split,
// bulk-copy double-buffered superstages (256 k each).
// Warp w: mt = w&3 (m16 tile), kh = w>>2 (k16 quarter of each 64-k block).
// myrow: per-thread X row base (valid for tid<64). wbase: W split source.
// ============================================================
__device__ __forceinline__ void gemm_core(char* sm, const char* myrow,
                                          const char* wbase, int tid,
                                          float* red, ull* mbs)
{
    const int w = tid >> 5, lane = tid & 31;
    const int mt = w & 3, kh = w >> 2;
    const int q = lane >> 2, c = lane & 3;
    const uint32_t smb = s2u(sm);
    const uint32_t mb0 = s2u(&mbs[0]), mb1 = s2u(&mbs[1]);

    if (tid == 0) { MB_INIT(mb0, 1); MB_INIT(mb1, 1); }
    __syncthreads();

    // upfront superstages 0, 1
    if (tid < 64) {
        bulkcp(smb + tid * XROW_B, myrow, 1024, mb0);
        bulkcp(smb + SLOT_B + tid * XROW_B, myrow + 1024, 1024, mb1);
    } else if (tid == 64) {
        MB_EXPECT(mb0, TXB);
        bulkcp(smb + W_OFF, wbase, WSUP_B, mb0);
        MB_EXPECT(mb1, TXB);
        bulkcp(smb + SLOT_B + W_OFF, wbase + WSUP_B, WSUP_B, mb1);
    }

    // ---- A fragment offsets (within sub-stage 0; + ss*256) ----
    uint32_t offA[4];
#pragma unroll
    for (int j = 0; j < 4; j++) {
        const int row = mt * 16 + q + (j & 1) * 8;
        const int kp = kh * 8 + c + (j >> 1) * 4;
        offA[j] = row * XROW_B + kp * 8;
    }
    // ---- B fragment offsets (hi; lo = +3072): [nt][b01] ----
    uint32_t offB[2][2];
#pragma unroll
    for (int nt = 0; nt < 2; nt++) {
        const int n = nt * 8 + q;
        offB[nt][0] = W_OFF + ((kh * 8 + c) * 24 + n) * 4;
        offB[nt][1] = W_OFF + ((kh * 8 + c + 4) * 24 + n) * 4;
    }

    float acc[2][4];
#pragma unroll
    for (int nt = 0; nt < 2; nt++)
#pragma unroll
        for (int i = 0; i < 4; i++) acc[nt][i] = 0.f;

    for (int S = 0; S < NSUP; S++) {
        const uint32_t slot = S & 1;
        mb_wait(slot ? mb1 : mb0, (S >> 1) & 1);

        const char* bb = sm + slot * SLOT_B;
#pragma unroll
        for (int ss = 0; ss < 4; ss++) {
            const uint32_t ao = ss * 256, bo = ss * 6144;   // FIX: 64 k = 256B per row
            uint32_t ah[4], al[4];
#pragma unroll
            for (int j = 0; j < 4; j++) {
                float2 v = *(const float2*)(bb + offA[j] + ao);
                split2(v.x, v.y, ah[j], al[j]);
            }
#pragma unroll
            for (int nt = 0; nt < 2; nt++) {
                const uint32_t bh0 = *(const uint32_t*)(bb + offB[nt][0] + bo);
                const uint32_t bh1 = *(const uint32_t*)(bb + offB[nt][1] + bo);
                const uint32_t bl0 = *(const uint32_t*)(bb + offB[nt][0] + bo + 3072);
                const uint32_t bl1 = *(const uint32_t*)(bb + offB[nt][1] + bo + 3072);
                mma16(acc[nt], ah, bh0, bh1);   // ah*bh
                mma16(acc[nt], ah, bl0, bl1);   // ah*bl
                mma16(acc[nt], al, bh0, bh1);   // al*bh  (al*bl dropped)
            }
        }
        __syncthreads();        // slot fully consumed by all threads
        if (S + 2 < NSUP) {
            const uint32_t mbn = slot ? mb1 : mb0;
            if (tid < 64) {
                bulkcp(smb + slot * SLOT_B + tid * XROW_B,
                       myrow + (size_t)(S + 2) * 1024, 1024, mbn);
            } else if (tid == 64) {
                MB_EXPECT(mbn, TXB);
                bulkcp(smb + slot * SLOT_B + W_OFF,
                       wbase + (size_t)(S + 2) * WSUP_B, WSUP_B, mbn);
            }
        }
    }

    // ---- cross-kh reduction (4 slices) into red[64][17] ----
    for (int step = 0; step < 4; step++) {
        if (kh == step) {
#pragma unroll
            for (int nt = 0; nt < 2; nt++) {
                const int r0 = mt * 16 + q, cc = nt * 8 + 2 * c;
                if (step == 0) {
                    red[r0 * 17 + cc]           = acc[nt][0];
                    red[r0 * 17 + cc + 1]       = acc[nt][1];
                    red[(r0 + 8) * 17 + cc]     = acc[nt][2];
                    red[(r0 + 8) * 17 + cc + 1] = acc[nt][3];
                } else {
                    red[r0 * 17 + cc]           += acc[nt][0];
                    red[r0 * 17 + cc + 1]       += acc[nt][1];
                    red[(r0 + 8) * 17 + cc]     += acc[nt][2];
                    red[(r0 + 8) * 17 + cc + 1] += acc[nt][3];
                }
            }
        }
        __syncthreads();
    }
}

// ============================================================
// Kernel 1: group-gate GEMM + softmax/argmax/sums/hist
// ============================================================
__global__ void __launch_bounds__(NTHR, 1)
k_gemm1(const float* __restrict__ X)
{
    extern __shared__ __align__(16) char sm[];
    __shared__ ull mbs[2];
    __shared__ int shist[NG];
    const int tid = threadIdx.x;
    if (tid < NG) shist[tid] = 0;

    const char* myrow = (const char*)(X + (size_t)(blockIdx.x * BM + (tid & 63)) * HID);
    float* red = (float*)sm;
    gemm_core(sm, myrow, (const char*)d_w1s, tid, red, mbs);

    float* pb = (float*)(sm + 4608);   // [64][17]
    if (tid < BM) {
        float lg[NG];
#pragma unroll
        for (int g = 0; g < NG; g++) lg[g] = red[tid * 17 + g];
        float mx = lg[0];
        int gi = 0;
#pragma unroll
        for (int g = 1; g < NG; g++)
            if (lg[g] > mx) { mx = lg[g]; gi = g; }
        float p[NG], ss = 0.f;
#pragma unroll
        for (int g = 0; g < NG; g++) { p[g] = __expf(lg[g] - mx); ss += p[g]; }
        const float inv = 1.0f / ss;
#pragma unroll
        for (int g = 0; g < NG; g++) pb[tid * 17 + g] = p[g] * inv;
        d_gsel[blockIdx.x * BM + tid] = gi;
        atomicAdd(&shist[gi], 1);
    }
    __syncthreads();
    if (tid < NG) {
        float s = 0.f;
        for (int t = 0; t < BM; t++) s += pb[t * 17 + tid];
        atomicAdd(&d_gsum[tid], s);
        atomicAdd(&d_gcount[tid], shist[tid]);
    }
}

// ============================================================
// Scatter with local prefix
// ============================================================
__global__ void k_scatter()
{
    __shared__ int cnt[NG], base[NG];
    const int tid = threadIdx.x;
    if (tid < NG) cnt[tid] = 0;
    __syncthreads();
    const int n = blockIdx.x * blockDim.x + tid;
    const int g = d_gsel[n];
    const int rr = atomicAdd(&cnt[g], 1);
    __syncthreads();
    if (tid < NG) {
        int goff = 0;
        for (int h = 0; h < NG; h++) {
            int c = d_gcount[h];
            if (h < tid) goff += c;
        }
        base[tid] = goff + atomicAdd(&d_gcur[tid], cnt[tid]);
    }
    __syncthreads();
    d_perm[base[g] + rr] = n;
}

// ============================================================
// Kernel 2: mini-gate GEMM (gathered rows) + top-4 epilogue
// ============================================================
__global__ void __launch_bounds__(NTHR, 1)
k_gemm2(const float* __restrict__ X, float* __restrict__ out)
{
    const int g = blockIdx.y;
    const int cnt = d_gcount[g];
    const int start = blockIdx.x * BM;
    if (start >= cnt) return;
    const int nvalid = min(BM, cnt - start);

    extern __shared__ __align__(16) char sm[];
    __shared__ ull mbs[2];
    __shared__ int rows_s[BM];
    const int tid = threadIdx.x;
    if (tid == 0) {            // local prefix: offset of group g
        int off = 0;
        for (int h = 0; h < NG; h++) {
            int c = d_gcount[h];
            if (h < g) off += c;
        }
        rows_s[0] = off;       // temp
    }
    __syncthreads();
    const int off = rows_s[0];
    __syncthreads();
    if (tid < BM) {
        int ix = start + tid;
        if (ix >= cnt) ix = cnt - 1;   // clamp: duplicate rows, discarded
        rows_s[tid] = d_perm[off + ix];
    }
    __syncthreads();

    const char* myrow = (const char*)(X + (size_t)rows_s[tid & 63] * HID);
    const char* wbase = (const char*)(d_wms + (size_t)g * (128 * WSTG_W));
    float* red = (float*)sm;
    gemm_core(sm, myrow, wbase, tid, red, mbs);

    float* pb = (float*)(sm + 4608);   // [64][17]
    if (tid < BM) {
        const bool valid = (tid < nvalid);
        float lg[NE];
#pragma unroll
        for (int e = 0; e < NE; e++) lg[e] = red[tid * 17 + e];
        float mx = lg[0];
#pragma unroll
        for (int e = 1; e < NE; e++) mx = fmaxf(mx, lg[e]);
        float ex[NE], ss = 0.f;
#pragma unroll
        for (int e = 0; e < NE; e++) { ex[e] = __expf(lg[e] - mx); ss += ex[e]; }
        const float inv = 1.0f / ss;
#pragma unroll
        for (int e = 0; e < NE; e++) pb[tid * 17 + e] = valid ? ex[e] * inv : 0.f;

        if (valid) {
            // top-4 by logit; strict > keeps lowest index on ties (lax.top_k order)
            float cur[NE];
#pragma unroll
            for (int e = 0; e < NE; e++) cur[e] = lg[e];
            int eidx[4];
            float ev[4], den = 0.f;
#pragma unroll
            for (int j = 0; j < 4; j++) {
                float best = -3.4e38f;
                int bi = 0;
#pragma unroll
                for (int e = 0; e < NE; e++)
                    if (cur[e] > best) { best = cur[e]; bi = e; }
                cur[bi] = -3.4e38f;
                eidx[j] = bi;
                ev[j] = ex[bi];
                den += ex[bi];
            }
            // group prob cancels in normalization: final = ex_j / sum(top4 ex)
            const float invd = 1.0f / den;
            const int n = rows_s[tid];
#pragma unroll
            for (int j = 0; j < 4; j++) {
                out[(size_t)n * 4 + j] = ev[j] * invd;
                out[(size_t)N_TOK * 4 + (size_t)n * 4 + j] = (float)(g * NE + eidx[j]);
            }
        }
    }
    __syncthreads();
    if (tid < NE) {
        float s = 0.f;
        for (int t = 0; t < BM; t++) s += pb[t * 17 + tid];
        atomicAdd(&d_msum[tid], s);
    }
}

// ============================================================
// Finalize: aux loss
// ============================================================
__global__ void k_final(float* __restrict__ out, int out_size)
{
    if (threadIdx.x == 0) {
        float a = 0.f;
        for (int i = 0; i < NG; i++) { float x = d_gsum[i] / (float)N_TOK; a += x * x; }
        for (int i = 0; i < NE; i++) { float x = d_msum[i] / (float)N_TOK; a += x * x; }
        out[out_size - 1] = a;
    }
}

// ============================================================
extern "C" void kernel_launch(void* const* d_in, const int* in_sizes, int n_in,
                              void* d_out, int out_size)
{
    const float* X  = (const float*)d_in[0];  // hidden_states [N, H]
    const float* W1 = (const float*)d_in[1];  // group_gate_w  [16, H]
    const float* WM = (const float*)d_in[2];  // mini_gates    [16, H, 16]
    float* out = (float*)d_out;               // [probs N*4 | indices N*4 | aux]

    cudaFuncSetAttribute(k_gemm1, cudaFuncAttributeMaxDynamicSharedMemorySize, SMEM_DYN);
    cudaFuncSetAttribute(k_gemm2, cudaFuncAttributeMaxDynamicSharedMemorySize, SMEM_DYN);

    k_prep<<<4352, 256>>>(W1, WM);                                // launch 1
    k_gemm1<<<N_TOK / BM, NTHR, SMEM_DYN>>>(X);                   // launch 2
    k_scatter<<<N_TOK / 256, 256>>>();                            // launch 3
    k_gemm2<<<dim3(N_TOK / BM, NG), NTHR, SMEM_DYN>>>(X, out);    // launch 4 (ncu slot)
    k_final<<<1, 32>>>(out, out_size);                            // launch 5
}